// round 15
// baseline (speedup 1.0000x reference)
#include <cuda_runtime.h>
#include <cstdint>

// TinyRNN: B=4096, T=2048, I=1, H=12, O=2
// 4 lanes/group; lane k owns rows {3k..3k+2} of TWO batches (A,B); 8 groups/
// warp -> 16 batches/warp; 64-thread CTAs (32 batches); grid=128 -> 256 warps.
// Exchange via same-warp shared memory, NO syncwarp (validated R11-R13),
// LANE-MAJOR slots (float m' = 4*i + k); ld.shared.b64 -> f32x2 operands;
// arrival-ordered fma2 trees; tanh via MUFU.TANH. Two independent chains per
// lane overlap: smem exchange has no SHFL-rt wall (R9's failure mode).

#define T_TOTAL 2048
#define NCHUNK  32
#define CH      64
#define XSTRIDE 68   // 64 + 4 pad
#define EXSTRIDE 20  // floats per batch slot (80B: 16B-aligned, conflict-free)

__device__ __forceinline__ uint64_t pack2(float lo, float hi) {
    uint64_t r; asm("mov.b64 %0, {%1, %2};" : "=l"(r) : "f"(lo), "f"(hi)); return r;
}
__device__ __forceinline__ void unpack2(uint64_t v, float &lo, float &hi) {
    asm("mov.b64 {%0, %1}, %2;" : "=f"(lo), "=f"(hi) : "l"(v));
}
__device__ __forceinline__ uint64_t mul2(uint64_t a, uint64_t b) {
    uint64_t r; asm("mul.rn.f32x2 %0, %1, %2;" : "=l"(r) : "l"(a), "l"(b)); return r;
}
__device__ __forceinline__ uint64_t fma2(uint64_t a, uint64_t b, uint64_t c) {
    uint64_t r; asm("fma.rn.f32x2 %0, %1, %2, %3;" : "=l"(r) : "l"(a), "l"(b), "l"(c)); return r;
}
__device__ __forceinline__ uint64_t add2(uint64_t a, uint64_t b) {
    uint64_t r; asm("add.rn.f32x2 %0, %1, %2;" : "=l"(r) : "l"(a), "l"(b)); return r;
}
__device__ __forceinline__ float tanhf_hw(float x) {
    float r; asm("tanh.approx.f32 %0, %1;" : "=f"(r) : "f"(x)); return r;
}

__global__ void __launch_bounds__(64, 1) tinyrnn_kernel(
    const float* __restrict__ x,       // [4096, 2048, 1]
    const float* __restrict__ W_ih,    // [12, 1]
    const float* __restrict__ W_hh,    // [12, 12]
    const float* __restrict__ b_ih,    // [12]
    const float* __restrict__ b_hh,    // [12]
    const float* __restrict__ W_head,  // [2, 12]
    const float* __restrict__ b_head,  // [2]
    float* __restrict__ out)           // [4096, 2]
{
    __shared__ float sx[2][32 * XSTRIDE];
    __shared__ __align__(16) float sex[32 * EXSTRIDE];

    const int tid  = threadIdx.x;            // 0..63
    const int lane = tid & 31;
    const int warp = tid >> 5;                // 0..1
    const int k    = lane & 3;                // lane within 4-lane group
    const int g    = lane >> 2;               // group within warp (0..7)
    const int bicA = warp * 16 + g;           // batch A in CTA
    const int bicB = bicA + 8;                // batch B in CTA
    const int batchA = blockIdx.x * 32 + bicA;
    const int batchB = blockIdx.x * 32 + bicB;

    // weights per owned row r=3k+i, lane-major pairs (shared by A and B):
    // quad q pair a = cols (q, 3+q) [lanes 0,1]; pair b = cols (6+q, 9+q)
    uint64_t WA[3][3], WB[3][3];
    float A[3], Bx[3];
#pragma unroll
    for (int i = 0; i < 3; i++) {
        const int r = 3 * k + i;
#pragma unroll
        for (int q = 0; q < 3; q++) {
            WA[i][q] = pack2(W_hh[r * 12 + q],     W_hh[r * 12 + 3 + q]);
            WB[i][q] = pack2(W_hh[r * 12 + 6 + q], W_hh[r * 12 + 9 + q]);
        }
        A[i]  = b_ih[r] + b_hh[r];
        Bx[i] = W_ih[r];
    }

    // exchange slots: float m' = 4*i + k (lane-major), one slot per batch
    const unsigned exA = (unsigned)__cvta_generic_to_shared(&sex[bicA * EXSTRIDE]);
    const unsigned exB = (unsigned)__cvta_generic_to_shared(&sex[bicB * EXSTRIDE]);
    const unsigned sA0 = exA + 4u * (unsigned)k, sA1 = sA0 + 16u, sA2 = sA0 + 32u;
    const unsigned sB0 = exB + 4u * (unsigned)k, sB1 = sB0 + 16u, sB2 = sB0 + 32u;

    const float* xcta = x + (size_t)blockIdx.x * 32 * T_TOTAL;

    // --- cp.async chunk prefetch: 32 batches x 64 steps = 512 float4 ---
    auto prefetch = [&](int c, int buf) {
#pragma unroll
        for (int rr = 0; rr < 8; rr++) {
            int flat = rr * 64 + tid;        // 0..511
            int b    = flat >> 4;
            int q    = flat & 15;
            const float* src = xcta + (size_t)b * T_TOTAL + c * CH + q * 4;
            unsigned dst = (unsigned)__cvta_generic_to_shared(
                &sx[buf][b * XSTRIDE + q * 4]);
            asm volatile("cp.async.ca.shared.global [%0], [%1], 16;\n"
                         :: "r"(dst), "l"(src));
        }
        asm volatile("cp.async.commit_group;\n");
    };

    prefetch(0, 0);

    float hA0 = 0.0f, hA1 = 0.0f, hA2 = 0.0f;
    float hB0 = 0.0f, hB1 = 0.0f, hB2 = 0.0f;

    for (int c = 0; c < NCHUNK; c++) {
        const int cur = c & 1;
        if (c + 1 < NCHUNK) {
            prefetch(c + 1, cur ^ 1);
            asm volatile("cp.async.wait_group 1;\n");
        } else {
            asm volatile("cp.async.wait_group 0;\n");
        }
        __syncthreads();

        const float* xsA = &sx[cur][bicA * XSTRIDE];
        const float* xsB = &sx[cur][bicB * XSTRIDE];

#pragma unroll 2
        for (int tt = 0; tt < CH; tt++) {
            // A's train first, B's right behind (same-warp MIO in-order).
            uint64_t PA0a, PA0b, PA1a, PA1b, PA2a, PA2b;
            uint64_t PB0a, PB0b, PB1a, PB1b, PB2a, PB2b;
            asm volatile("st.shared.f32 [%0], %1;" :: "r"(sA0), "f"(hA0));
            asm volatile("ld.shared.b64 %0, [%1];" : "=l"(PA0a) : "r"(exA));
            asm volatile("ld.shared.b64 %0, [%1];" : "=l"(PA0b) : "r"(exA + 8u));
            asm volatile("st.shared.f32 [%0], %1;" :: "r"(sA1), "f"(hA1));
            asm volatile("ld.shared.b64 %0, [%1];" : "=l"(PA1a) : "r"(exA + 16u));
            asm volatile("ld.shared.b64 %0, [%1];" : "=l"(PA1b) : "r"(exA + 24u));
            asm volatile("st.shared.f32 [%0], %1;" :: "r"(sA2), "f"(hA2));
            asm volatile("ld.shared.b64 %0, [%1];" : "=l"(PA2a) : "r"(exA + 32u));
            asm volatile("ld.shared.b64 %0, [%1];" : "=l"(PA2b) : "r"(exA + 40u));

            asm volatile("st.shared.f32 [%0], %1;" :: "r"(sB0), "f"(hB0));
            asm volatile("ld.shared.b64 %0, [%1];" : "=l"(PB0a) : "r"(exB));
            asm volatile("ld.shared.b64 %0, [%1];" : "=l"(PB0b) : "r"(exB + 8u));
            asm volatile("st.shared.f32 [%0], %1;" :: "r"(sB1), "f"(hB1));
            asm volatile("ld.shared.b64 %0, [%1];" : "=l"(PB1a) : "r"(exB + 16u));
            asm volatile("ld.shared.b64 %0, [%1];" : "=l"(PB1b) : "r"(exB + 24u));
            asm volatile("st.shared.f32 [%0], %1;" :: "r"(sB2), "f"(hB2));
            asm volatile("ld.shared.b64 %0, [%1];" : "=l"(PB2a) : "r"(exB + 32u));
            asm volatile("ld.shared.b64 %0, [%1];" : "=l"(PB2b) : "r"(exB + 40u));

            // x + bias terms (independent; fill LDS shadow)
            const float xtA = xsA[tt];
            const float xtB = xsB[tt];
            const uint64_t UA[3] = {
                pack2(fmaf(xtA, Bx[0], A[0]), 0.0f),
                pack2(fmaf(xtA, Bx[1], A[1]), 0.0f),
                pack2(fmaf(xtA, Bx[2], A[2]), 0.0f)};
            const uint64_t UB[3] = {
                pack2(fmaf(xtB, Bx[0], A[0]), 0.0f),
                pack2(fmaf(xtB, Bx[1], A[1]), 0.0f),
                pack2(fmaf(xtB, Bx[2], A[2]), 0.0f)};

            float hnA[3], hnB[3];
#pragma unroll
            for (int i = 0; i < 3; i++) {
                uint64_t aA = fma2(WA[i][0], PA0a, UA[i]);
                uint64_t bA = mul2(WB[i][0], PA0b);
                aA = fma2(WA[i][1], PA1a, aA);
                bA = fma2(WB[i][1], PA1b, bA);
                aA = fma2(WA[i][2], PA2a, aA);
                bA = fma2(WB[i][2], PA2b, bA);
                float lo, hi;
                unpack2(add2(aA, bA), lo, hi);
                hnA[i] = tanhf_hw(lo + hi);
            }
#pragma unroll
            for (int i = 0; i < 3; i++) {
                uint64_t aB = fma2(WA[i][0], PB0a, UB[i]);
                uint64_t bB = mul2(WB[i][0], PB0b);
                aB = fma2(WA[i][1], PB1a, aB);
                bB = fma2(WB[i][1], PB1b, bB);
                aB = fma2(WA[i][2], PB2a, aB);
                bB = fma2(WB[i][2], PB2b, bB);
                float lo, hi;
                unpack2(add2(aB, bB), lo, hi);
                hnB[i] = tanhf_hw(lo + hi);
            }
            hA0 = hnA[0]; hA1 = hnA[1]; hA2 = hnA[2];
            hB0 = hnB[0]; hB1 = hnB[1]; hB2 = hnB[2];
        }
        __syncthreads();
    }

    // --- head: rebuild full h per batch via shfl (one-time) ---
    float gA[12], gB[12];
    gA[3 * k + 0] = hA0; gA[3 * k + 1] = hA1; gA[3 * k + 2] = hA2;
    gB[3 * k + 0] = hB0; gB[3 * k + 1] = hB1; gB[3 * k + 2] = hB2;
#pragma unroll
    for (int d = 1; d < 4; d++) {
        const int p = k ^ d;
        gA[3 * p + 0] = __shfl_xor_sync(0xffffffffu, hA0, d, 4);
        gA[3 * p + 1] = __shfl_xor_sync(0xffffffffu, hA1, d, 4);
        gA[3 * p + 2] = __shfl_xor_sync(0xffffffffu, hA2, d, 4);
        gB[3 * p + 0] = __shfl_xor_sync(0xffffffffu, hB0, d, 4);
        gB[3 * p + 1] = __shfl_xor_sync(0xffffffffu, hB1, d, 4);
        gB[3 * p + 2] = __shfl_xor_sync(0xffffffffu, hB2, d, 4);
    }

    if (k == 0) {
        float o0A = b_head[0], o1A = b_head[1];
        float o0B = b_head[0], o1B = b_head[1];
#pragma unroll
        for (int m = 0; m < 12; m++) {
            o0A = fmaf(W_head[m],      gA[m], o0A);
            o1A = fmaf(W_head[12 + m], gA[m], o1A);
            o0B = fmaf(W_head[m],      gB[m], o0B);
            o1B = fmaf(W_head[12 + m], gB[m], o1B);
        }
        out[batchA * 2 + 0] = o0A;
        out[batchA * 2 + 1] = o1A;
        out[batchB * 2 + 0] = o0B;
        out[batchB * 2 + 1] = o1B;
    }
}

extern "C" void kernel_launch(void* const* d_in, const int* in_sizes, int n_in,
                              void* d_out, int out_size)
{
    const float* x      = (const float*)d_in[0];
    const float* W_ih   = (const float*)d_in[1];
    const float* W_hh   = (const float*)d_in[2];
    const float* b_ih   = (const float*)d_in[3];
    const float* b_hh   = (const float*)d_in[4];
    const float* W_head = (const float*)d_in[5];
    const float* b_head = (const float*)d_in[6];
    float* out = (float*)d_out;

    tinyrnn_kernel<<<128, 64>>>(x, W_ih, W_hh, b_ih, b_hh, W_head, b_head, out);
}

// round 16
// speedup vs baseline: 1.3054x; 1.3054x over previous
#include <cuda_runtime.h>
#include <cstdint>

// TinyRNN: B=4096, T=2048, I=1, H=12, O=2
// 12 lanes/batch, 1 row/lane. Warp = 2 real groups (lanes 0-11, 12-23) +
// mirror group (lanes 24-31 duplicate group 0 into a dummy slot; no
// divergence). 128-thread CTAs = 8 batches; grid=512 -> 2048 warps
// (~3.4/SMSP): chains overlap ACROSS warps (in-warp ILP proven dead R9/R15).
// Exchange: ONE STS publishes all 12 h; 6 LDS.b64 -> f32x2 pairs (global
// order); same-warp MIO in-order, NO syncwarp (validated R11-R13).
// Chain: tanh(16) -> STS -> LDS -> 6 fma2 (2 chains) + add2 + hadd + tanh.

#define T_TOTAL 2048
#define NCHUNK  32
#define CH      64
#define XSTRIDE 68    // 64 + 4 pad
#define EXSTRIDE 20   // floats per slot (80B): banks (20s+j) conflict-free

__device__ __forceinline__ uint64_t pack2(float lo, float hi) {
    uint64_t r; asm("mov.b64 %0, {%1, %2};" : "=l"(r) : "f"(lo), "f"(hi)); return r;
}
__device__ __forceinline__ void unpack2(uint64_t v, float &lo, float &hi) {
    asm("mov.b64 {%0, %1}, %2;" : "=f"(lo), "=f"(hi) : "l"(v));
}
__device__ __forceinline__ uint64_t mul2(uint64_t a, uint64_t b) {
    uint64_t r; asm("mul.rn.f32x2 %0, %1, %2;" : "=l"(r) : "l"(a), "l"(b)); return r;
}
__device__ __forceinline__ uint64_t fma2(uint64_t a, uint64_t b, uint64_t c) {
    uint64_t r; asm("fma.rn.f32x2 %0, %1, %2, %3;" : "=l"(r) : "l"(a), "l"(b), "l"(c)); return r;
}
__device__ __forceinline__ uint64_t add2(uint64_t a, uint64_t b) {
    uint64_t r; asm("add.rn.f32x2 %0, %1, %2;" : "=l"(r) : "l"(a), "l"(b)); return r;
}
__device__ __forceinline__ float tanhf_hw(float x) {
    float r; asm("tanh.approx.f32 %0, %1;" : "=f"(r) : "f"(x)); return r;
}

__global__ void __launch_bounds__(128) tinyrnn_kernel(
    const float* __restrict__ x,       // [4096, 2048, 1]
    const float* __restrict__ W_ih,    // [12, 1]
    const float* __restrict__ W_hh,    // [12, 12]
    const float* __restrict__ b_ih,    // [12]
    const float* __restrict__ b_hh,    // [12]
    const float* __restrict__ W_head,  // [2, 12]
    const float* __restrict__ b_head,  // [2]
    float* __restrict__ out)           // [4096, 2]
{
    __shared__ float sx[2][8 * XSTRIDE];                  // 8 batches x chunk
    __shared__ __align__(16) float sex[12 * EXSTRIDE];    // 12 slots (8 real + 4 dummy)

    const int tid  = threadIdx.x;
    const int lane = tid & 31;
    const int warp = tid >> 5;               // 0..3
    const int grp  = lane / 12;              // 0,1 real; 2 = mirror
    const int j    = lane - 12 * grp;        // row owned (0..11)
    const int slot = warp * 3 + grp;         // 0..11
    const int bic  = warp * 2 + (grp < 2 ? grp : 0);   // batch in CTA (mirror->A)
    const int batch = blockIdx.x * 8 + bic;

    // weights for row j: 6 packed column pairs (global order)
    uint64_t Wc[6];
#pragma unroll
    for (int q = 0; q < 6; q++)
        Wc[q] = pack2(W_hh[j * 12 + 2 * q], W_hh[j * 12 + 2 * q + 1]);
    const float A  = b_ih[j] + b_hh[j];
    const float Bx = W_ih[j];

    // exchange addresses
    const unsigned exb = (unsigned)__cvta_generic_to_shared(&sex[slot * EXSTRIDE]);
    const unsigned stj = exb + 4u * (unsigned)j;

    const float* xcta = x + (size_t)blockIdx.x * 8 * T_TOTAL;

    // cp.async chunk prefetch: 8 batches x 64 steps = 128 float4, 1/thread
    auto prefetch = [&](int c, int buf) {
        int b = tid >> 4;                    // 0..7
        int q = tid & 15;                    // float4 within chunk
        const float* src = xcta + (size_t)b * T_TOTAL + c * CH + q * 4;
        unsigned dst = (unsigned)__cvta_generic_to_shared(
            &sx[buf][b * XSTRIDE + q * 4]);
        asm volatile("cp.async.ca.shared.global [%0], [%1], 16;\n"
                     :: "r"(dst), "l"(src));
        asm volatile("cp.async.commit_group;\n");
    };

    prefetch(0, 0);

    float h = 0.0f;    // own row

    for (int c = 0; c < NCHUNK; c++) {
        const int cur = c & 1;
        if (c + 1 < NCHUNK) {
            prefetch(c + 1, cur ^ 1);
            asm volatile("cp.async.wait_group 1;\n");
        } else {
            asm volatile("cp.async.wait_group 0;\n");
        }
        __syncthreads();

        const float* xs = &sx[cur][bic * XSTRIDE];

#pragma unroll 4
        for (int tt = 0; tt < CH; tt++) {
            // publish own h (ONE STS instr covers all lanes), read 6 pairs
            uint64_t P0, P1, P2, P3, P4, P5;
            asm volatile("st.shared.f32 [%0], %1;" :: "r"(stj), "f"(h));
            asm volatile("ld.shared.b64 %0, [%1];" : "=l"(P0) : "r"(exb));
            asm volatile("ld.shared.b64 %0, [%1];" : "=l"(P1) : "r"(exb + 8u));
            asm volatile("ld.shared.b64 %0, [%1];" : "=l"(P2) : "r"(exb + 16u));
            asm volatile("ld.shared.b64 %0, [%1];" : "=l"(P3) : "r"(exb + 24u));
            asm volatile("ld.shared.b64 %0, [%1];" : "=l"(P4) : "r"(exb + 32u));
            asm volatile("ld.shared.b64 %0, [%1];" : "=l"(P5) : "r"(exb + 40u));

            // u-term in the LDS shadow
            const float xt = xs[tt];
            const uint64_t U = pack2(fmaf(xt, Bx, A), 0.0f);

            // two 3-deep fma2 chains, arrival-ordered
            uint64_t a = fma2(Wc[0], P0, U);
            uint64_t b = mul2(Wc[1], P1);
            a = fma2(Wc[2], P2, a);
            b = fma2(Wc[3], P3, b);
            a = fma2(Wc[4], P4, a);
            b = fma2(Wc[5], P5, b);
            float lo, hi;
            unpack2(add2(a, b), lo, hi);
            h = tanhf_hw(lo + hi);
        }
        __syncthreads();
    }

    // --- head: publish final h, lane j==0 of real groups computes output ---
    asm volatile("st.shared.f32 [%0], %1;" :: "r"(stj), "f"(h));
    // same-warp in-order: following LDS (same lane issues them) sees all
    // lanes' STS of this warp (single STS instruction above).
    if (j == 0 && grp < 2) {
        uint64_t Q0, Q1, Q2, Q3, Q4, Q5;
        asm volatile("ld.shared.b64 %0, [%1];" : "=l"(Q0) : "r"(exb));
        asm volatile("ld.shared.b64 %0, [%1];" : "=l"(Q1) : "r"(exb + 8u));
        asm volatile("ld.shared.b64 %0, [%1];" : "=l"(Q2) : "r"(exb + 16u));
        asm volatile("ld.shared.b64 %0, [%1];" : "=l"(Q3) : "r"(exb + 24u));
        asm volatile("ld.shared.b64 %0, [%1];" : "=l"(Q4) : "r"(exb + 32u));
        asm volatile("ld.shared.b64 %0, [%1];" : "=l"(Q5) : "r"(exb + 40u));
        float g[12];
        unpack2(Q0, g[0], g[1]);
        unpack2(Q1, g[2], g[3]);
        unpack2(Q2, g[4], g[5]);
        unpack2(Q3, g[6], g[7]);
        unpack2(Q4, g[8], g[9]);
        unpack2(Q5, g[10], g[11]);
        float o0 = b_head[0];
        float o1 = b_head[1];
#pragma unroll
        for (int m = 0; m < 12; m++) {
            o0 = fmaf(W_head[m],      g[m], o0);
            o1 = fmaf(W_head[12 + m], g[m], o1);
        }
        out[batch * 2 + 0] = o0;
        out[batch * 2 + 1] = o1;
    }
}

extern "C" void kernel_launch(void* const* d_in, const int* in_sizes, int n_in,
                              void* d_out, int out_size)
{
    const float* x      = (const float*)d_in[0];
    const float* W_ih   = (const float*)d_in[1];
    const float* W_hh   = (const float*)d_in[2];
    const float* b_ih   = (const float*)d_in[3];
    const float* b_hh   = (const float*)d_in[4];
    const float* W_head = (const float*)d_in[5];
    const float* b_head = (const float*)d_in[6];
    float* out = (float*)d_out;

    tinyrnn_kernel<<<512, 128>>>(x, W_ih, W_hh, b_ih, b_hh, W_head, b_head, out);
}

// round 17
// speedup vs baseline: 1.4313x; 1.0964x over previous
#include <cuda_runtime.h>
#include <cstdint>

// TinyRNN: B=4096, T=2048, I=1, H=12, O=2
// 12 lanes/batch, 1 row/lane. Warp = 2 real groups (lanes 0-11, 12-23);
// lanes 24-31 MIRROR group 0 (same slot, same addresses, same values -> no
// divergence, no dummy slot). 128-thread CTAs = 8 batches; grid=512 -> 2048
// warps (~3.4/SMSP): chains overlap ACROSS warps.
// MIO-minimized exchange (R16 showed L1=79% wavefront wall):
//   1 STS + 3x ld.shared.v2.b64 (each = TWO f32x2 operands, no movs)
//   + 0.5 x-loads/step (float2 per 2 steps)  => ~4.5 shared ops/warp-step.

#define T_TOTAL 2048
#define NCHUNK  32
#define CH      64
#define XSTRIDE 68    // 64 + 4 pad (8B-aligned rows)
#define EXSTRIDE 20   // floats per slot (80B): 16B-aligned, banks conflict-free

__device__ __forceinline__ uint64_t pack2(float lo, float hi) {
    uint64_t r; asm("mov.b64 %0, {%1, %2};" : "=l"(r) : "f"(lo), "f"(hi)); return r;
}
__device__ __forceinline__ void unpack2(uint64_t v, float &lo, float &hi) {
    asm("mov.b64 {%0, %1}, %2;" : "=f"(lo), "=f"(hi) : "l"(v));
}
__device__ __forceinline__ uint64_t mul2(uint64_t a, uint64_t b) {
    uint64_t r; asm("mul.rn.f32x2 %0, %1, %2;" : "=l"(r) : "l"(a), "l"(b)); return r;
}
__device__ __forceinline__ uint64_t fma2(uint64_t a, uint64_t b, uint64_t c) {
    uint64_t r; asm("fma.rn.f32x2 %0, %1, %2, %3;" : "=l"(r) : "l"(a), "l"(b), "l"(c)); return r;
}
__device__ __forceinline__ uint64_t add2(uint64_t a, uint64_t b) {
    uint64_t r; asm("add.rn.f32x2 %0, %1, %2;" : "=l"(r) : "l"(a), "l"(b)); return r;
}
__device__ __forceinline__ float tanhf_hw(float x) {
    float r; asm("tanh.approx.f32 %0, %1;" : "=f"(r) : "f"(x)); return r;
}

__global__ void __launch_bounds__(128) tinyrnn_kernel(
    const float* __restrict__ x,       // [4096, 2048, 1]
    const float* __restrict__ W_ih,    // [12, 1]
    const float* __restrict__ W_hh,    // [12, 12]
    const float* __restrict__ b_ih,    // [12]
    const float* __restrict__ b_hh,    // [12]
    const float* __restrict__ W_head,  // [2, 12]
    const float* __restrict__ b_head,  // [2]
    float* __restrict__ out)           // [4096, 2]
{
    __shared__ float sx[2][8 * XSTRIDE];                  // 8 batches x chunk
    __shared__ __align__(16) float sex[8 * EXSTRIDE];     // 8 real slots

    const int tid  = threadIdx.x;
    const int lane = tid & 31;
    const int warp = tid >> 5;               // 0..3
    const int grp0 = lane / 12;              // 0,1 real; 2 = mirror
    const int j    = lane - 12 * grp0;       // row owned (0..11 / 0..7 mirror)
    const int grp  = (grp0 == 2) ? 0 : grp0; // mirror aliases group 0
    const int slot = warp * 2 + grp;         // 0..7
    const int bic  = slot;                   // batch in CTA
    const int batch = blockIdx.x * 8 + bic;

    // weights for row j: 6 packed column pairs (global order)
    uint64_t Wc[6];
#pragma unroll
    for (int q = 0; q < 6; q++)
        Wc[q] = pack2(W_hh[j * 12 + 2 * q], W_hh[j * 12 + 2 * q + 1]);
    const float A  = b_ih[j] + b_hh[j];
    const float Bx = W_ih[j];

    // exchange addresses (mirror lanes: same as group-0 lanes -> broadcast)
    const unsigned exb = (unsigned)__cvta_generic_to_shared(&sex[slot * EXSTRIDE]);
    const unsigned stj = exb + 4u * (unsigned)j;

    const float* xcta = x + (size_t)blockIdx.x * 8 * T_TOTAL;

    // cp.async chunk prefetch: 8 batches x 64 steps = 128 float4, 1/thread
    auto prefetch = [&](int c, int buf) {
        int b = tid >> 4;                    // 0..7
        int q = tid & 15;                    // float4 within chunk
        const float* src = xcta + (size_t)b * T_TOTAL + c * CH + q * 4;
        unsigned dst = (unsigned)__cvta_generic_to_shared(
            &sx[buf][b * XSTRIDE + q * 4]);
        asm volatile("cp.async.ca.shared.global [%0], [%1], 16;\n"
                     :: "r"(dst), "l"(src));
        asm volatile("cp.async.commit_group;\n");
    };

    prefetch(0, 0);

    float h = 0.0f;    // own row

    for (int c = 0; c < NCHUNK; c++) {
        const int cur = c & 1;
        if (c + 1 < NCHUNK) {
            prefetch(c + 1, cur ^ 1);
            asm volatile("cp.async.wait_group 1;\n");
        } else {
            asm volatile("cp.async.wait_group 0;\n");
        }
        __syncthreads();

        const unsigned xsh = (unsigned)__cvta_generic_to_shared(
            &sx[cur][bic * XSTRIDE]);

#pragma unroll 2
        for (int tt = 0; tt < CH; tt += 2) {
            // one float2 x-load per 2 steps
            float xlo, xhi;
            asm volatile("ld.shared.v2.f32 {%0,%1}, [%2];"
                         : "=f"(xlo), "=f"(xhi) : "r"(xsh + 4u * (unsigned)tt));

#pragma unroll
            for (int s = 0; s < 2; s++) {
                const float xt = (s == 0) ? xlo : xhi;
                // publish own h; read 6 f32x2 operands via 3 LDS.128
                uint64_t P0, P1, P2, P3, P4, P5;
                asm volatile("st.shared.f32 [%0], %1;" :: "r"(stj), "f"(h));
                asm volatile("ld.shared.v2.b64 {%0,%1}, [%2];"
                             : "=l"(P0), "=l"(P1) : "r"(exb));
                asm volatile("ld.shared.v2.b64 {%0,%1}, [%2];"
                             : "=l"(P2), "=l"(P3) : "r"(exb + 16u));
                asm volatile("ld.shared.v2.b64 {%0,%1}, [%2];"
                             : "=l"(P4), "=l"(P5) : "r"(exb + 32u));

                const uint64_t U = pack2(fmaf(xt, Bx, A), 0.0f);

                // two 3-deep fma2 chains, arrival-ordered
                uint64_t a = fma2(Wc[0], P0, U);
                uint64_t b = mul2(Wc[1], P1);
                a = fma2(Wc[2], P2, a);
                b = fma2(Wc[3], P3, b);
                a = fma2(Wc[4], P4, a);
                b = fma2(Wc[5], P5, b);
                float lo, hi;
                unpack2(add2(a, b), lo, hi);
                h = tanhf_hw(lo + hi);
            }
        }
        __syncthreads();
    }

    // --- head: publish final h; lane j==0 of real groups computes output ---
    asm volatile("st.shared.f32 [%0], %1;" :: "r"(stj), "f"(h));
    if (j == 0 && grp0 < 2) {
        uint64_t Q0, Q1, Q2, Q3, Q4, Q5;
        asm volatile("ld.shared.v2.b64 {%0,%1}, [%2];"
                     : "=l"(Q0), "=l"(Q1) : "r"(exb));
        asm volatile("ld.shared.v2.b64 {%0,%1}, [%2];"
                     : "=l"(Q2), "=l"(Q3) : "r"(exb + 16u));
        asm volatile("ld.shared.v2.b64 {%0,%1}, [%2];"
                     : "=l"(Q4), "=l"(Q5) : "r"(exb + 32u));
        float g[12];
        unpack2(Q0, g[0], g[1]);
        unpack2(Q1, g[2], g[3]);
        unpack2(Q2, g[4], g[5]);
        unpack2(Q3, g[6], g[7]);
        unpack2(Q4, g[8], g[9]);
        unpack2(Q5, g[10], g[11]);
        float o0 = b_head[0];
        float o1 = b_head[1];
#pragma unroll
        for (int m = 0; m < 12; m++) {
            o0 = fmaf(W_head[m],      g[m], o0);
            o1 = fmaf(W_head[12 + m], g[m], o1);
        }
        out[batch * 2 + 0] = o0;
        out[batch * 2 + 1] = o1;
    }
}

extern "C" void kernel_launch(void* const* d_in, const int* in_sizes, int n_in,
                              void* d_out, int out_size)
{
    const float* x      = (const float*)d_in[0];
    const float* W_ih   = (const float*)d_in[1];
    const float* W_hh   = (const float*)d_in[2];
    const float* b_ih   = (const float*)d_in[3];
    const float* b_hh   = (const float*)d_in[4];
    const float* W_head = (const float*)d_in[5];
    const float* b_head = (const float*)d_in[6];
    float* out = (float*)d_out;

    tinyrnn_kernel<<<512, 128>>>(x, W_ih, W_hh, b_ih, b_hh, W_head, b_head, out);
}